// round 2
// baseline (speedup 1.0000x reference)
#include <cuda_runtime.h>

#define NL 4
#define BATCH 16384
#define WPB 16
#define THREADS 512
#define NBLK (BATCH / (WPB * 2))   // 512 blocks, 2 elements per warp
#define XPW_S 129                  // padded stride for transposed xpw (bank-conflict-free)
#define EPSV 1e-5f

typedef unsigned long long ull;

// ---------------- f32x2 helpers (FFMA2: 2x fp32 FMA rate on sm_103a) ----------------
__device__ __forceinline__ ull pk2(float lo, float hi) {
    ull r; asm("mov.b64 %0,{%1,%2};" : "=l"(r) : "f"(lo), "f"(hi)); return r;
}
__device__ __forceinline__ void upk2(ull v, float& lo, float& hi) {
    asm("mov.b64 {%0,%1},%2;" : "=f"(lo), "=f"(hi) : "l"(v));
}
__device__ __forceinline__ ull ffma2(ull a, ull b, ull c) {
    ull d; asm("fma.rn.f32x2 %0,%1,%2,%3;" : "=l"(d) : "l"(a), "l"(b), "l"(c)); return d;
}
__device__ __forceinline__ float warp_sum(float v) {
    v += __shfl_xor_sync(0xffffffffu, v, 16);
    v += __shfl_xor_sync(0xffffffffu, v, 8);
    v += __shfl_xor_sync(0xffffffffu, v, 4);
    v += __shfl_xor_sync(0xffffffffu, v, 2);
    v += __shfl_xor_sync(0xffffffffu, v, 1);
    return v;
}
__device__ __forceinline__ float half_sum(float v) {  // sum within each 16-lane half
    v += __shfl_xor_sync(0xffffffffu, v, 8);
    v += __shfl_xor_sync(0xffffffffu, v, 4);
    v += __shfl_xor_sync(0xffffffffu, v, 2);
    v += __shfl_xor_sync(0xffffffffu, v, 1);
    return v;
}
__device__ __forceinline__ float siluf(float v) {
    return __fdividef(v, 1.0f + __expf(-v));
}
__device__ __forceinline__ float softplusf(float v) {
    return fmaxf(v, 0.0f) + __logf(1.0f + __expf(-fabsf(v)));
}

// ------------- folded input-projection weights (written by prep kernel) -------------
__device__ float g_Wnr[12 * 64];
__device__ float g_bnr[64];
__device__ float g_Wr[4 * 64];
__device__ float g_br[64];

// One warp per output element; lanes split the 1000-long contraction.
__global__ void __launch_bounds__(256)
prep_kernel(const float* __restrict__ w_nr, const float* __restrict__ b_nr,
            const float* __restrict__ w_r,  const float* __restrict__ b_r,
            const float* __restrict__ w_in_nr, const float* __restrict__ b_in_nr,
            const float* __restrict__ w_in_r,  const float* __restrict__ b_in_r) {
    int W = blockIdx.x * 8 + (threadIdx.x >> 5);   // 0..1151
    int lane = threadIdx.x & 31;
    const float* vec; const float* mat; int o;
    if (W < 768)        { vec = w_nr + (W >> 6) * 1000;        mat = w_in_nr; o = W & 63; }
    else if (W < 832)   { vec = b_nr;                          mat = w_in_nr; o = W - 768; }
    else if (W < 1088)  { vec = w_r + ((W - 832) >> 6) * 1000; mat = w_in_r;  o = (W - 832) & 63; }
    else                { vec = b_r;                           mat = w_in_r;  o = W - 1088; }
    float a = 0.0f;
    for (int c = lane; c < 1000; c += 32)
        a = fmaf(vec[c], mat[c * 64 + o], a);
    a = warp_sum(a);
    if (lane == 0) {
        if (W < 768)       g_Wnr[W] = a;
        else if (W < 832)  g_bnr[W - 768] = a + b_in_nr[W - 768];
        else if (W < 1088) g_Wr[W - 832] = a;
        else               g_br[W - 1088] = a + b_in_r[W - 1088];
    }
}

// ---------------- shared memory layout (175 KB -> 1 block/SM) ----------------
struct __align__(16) Smem {
    float ipw[64 * 256];          // xz weights for current layer [i][j]
    float opw[128 * 64];          // out-proj weights [d][o]
    float xpwT[36 * XPW_S];       // transposed x-proj [j][d], stride 129
    float dtw[4 * 128];           // [r][d]
    float cw3[128];
    float cb[128];
    float dtb[128];
    float dskip[128];
    float lng[64];
    float lnb[64];
    float Wnr[12 * 64];
    float Wr[4 * 64];
    float bnr[64];
    float br[64];
    float xs[WPB][4][64];         // per-warp per-job x (also final-x for head)
    float sc[WPB][4][128];        // per-warp per-job scratch: xc, then y
};

__global__ void __launch_bounds__(THREADS, 1)
mamba_main(const float* __restrict__ xin,
           const float* __restrict__ ipw_g, const float* __restrict__ cw_g,
           const float* __restrict__ cb_g,  const float* __restrict__ xpw_g,
           const float* __restrict__ dtw_g, const float* __restrict__ dtb_g,
           const float* __restrict__ dskip_g, const float* __restrict__ opw_g,
           const float* __restrict__ lng_g, const float* __restrict__ lnb_g,
           const float* __restrict__ hw1, const float* __restrict__ hb1,
           const float* __restrict__ hw2, const float* __restrict__ hb2,
           float* __restrict__ out) {
    extern __shared__ __align__(16) char smem_raw[];
    Smem& s = *reinterpret_cast<Smem*>(smem_raw);

    const int t = threadIdx.x;
    const int w = t >> 5;
    const int lane = t & 31;
    const int e0 = (blockIdx.x * WPB + w) * 2;

    // ---- stage folded input-proj weights ----
    for (int i = t; i < 768; i += THREADS) s.Wnr[i] = g_Wnr[i];
    if (t < 256)      s.Wr[t] = g_Wr[t];
    else if (t < 320) s.bnr[t - 256] = g_bnr[t - 256];
    else if (t < 384) s.br[t - 320] = g_br[t - 320];
    __syncthreads();

    // ---- x0 = feat @ W_eff + b_eff ; jobs: 0=(e0,nr) 1=(e0,r) 2=(e1,nr) 3=(e1,r) ----
    // lane owns DM dims {2*lane, 2*lane+1}
    float x_[4][2];
    {
        float fe[2][16];
#pragma unroll
        for (int e = 0; e < 2; e++) {
            const float4* xp = (const float4*)(xin + (size_t)(e0 + e) * 16);
#pragma unroll
            for (int q = 0; q < 4; q++) {
                float4 v = xp[q];
                fe[e][4 * q + 0] = v.x; fe[e][4 * q + 1] = v.y;
                fe[e][4 * q + 2] = v.z; fe[e][4 * q + 3] = v.w;
            }
        }
        float2 bn = *(const float2*)&s.bnr[2 * lane];
        float2 bb = *(const float2*)&s.br[2 * lane];
        ull a0 = pk2(bn.x, bn.y), a2 = a0;
        ull a1 = pk2(bb.x, bb.y), a3 = a1;
#pragma unroll
        for (int f = 0; f < 12; f++) {
            float2 w2 = *(const float2*)&s.Wnr[f * 64 + 2 * lane];
            ull wp = pk2(w2.x, w2.y);
            a0 = ffma2(wp, pk2(fe[0][f], fe[0][f]), a0);
            a2 = ffma2(wp, pk2(fe[1][f], fe[1][f]), a2);
        }
#pragma unroll
        for (int f = 0; f < 4; f++) {
            float2 w2 = *(const float2*)&s.Wr[f * 64 + 2 * lane];
            ull wp = pk2(w2.x, w2.y);
            a1 = ffma2(wp, pk2(fe[0][12 + f], fe[0][12 + f]), a1);
            a3 = ffma2(wp, pk2(fe[1][12 + f], fe[1][12 + f]), a3);
        }
        upk2(a0, x_[0][0], x_[0][1]);
        upk2(a1, x_[1][0], x_[1][1]);
        upk2(a2, x_[2][0], x_[2][1]);
        upk2(a3, x_[3][0], x_[3][1]);
    }

    // ================= layer loop =================
#pragma unroll 1
    for (int l = 0; l < NL; l++) {
        __syncthreads();   // previous layer's weight reads done
        {
            const float4* srcI = (const float4*)(ipw_g + l * 16384);
            float4* dI = (float4*)s.ipw;
            for (int i = t; i < 4096; i += THREADS) dI[i] = srcI[i];
            const float4* srcO = (const float4*)(opw_g + l * 8192);
            float4* dO = (float4*)s.opw;
            for (int i = t; i < 2048; i += THREADS) dO[i] = srcO[i];
            for (int i = t; i < 4608; i += THREADS) {   // xpw[l][d][j] -> xpwT[j][d]
                int d = i / 36, j = i - d * 36;
                s.xpwT[j * XPW_S + d] = xpw_g[l * 4608 + i];
            }
            s.dtw[t] = dtw_g[l * 512 + t];
            if (t < 128)      s.cw3[t] = cw_g[(l * 128 + t) * 4 + 3];
            else if (t < 256) s.cb[t - 128] = cb_g[l * 128 + (t - 128)];
            else if (t < 384) s.dtb[t - 256] = dtb_g[l * 128 + (t - 256)];
            else              s.dskip[t - 384] = dskip_g[l * 128 + (t - 384)];
            if (t < 64)       s.lng[t] = lng_g[l * 64 + t];
            else if (t < 128) s.lnb[t - 64] = lnb_g[l * 64 + (t - 64)];
        }
        __syncthreads();

        // ---- stage x into smem for the 64->256 gemv ----
#pragma unroll
        for (int job = 0; job < 4; job++)
            *(float2*)&s.xs[w][job][2 * lane] = make_float2(x_[job][0], x_[job][1]);
        __syncwarp();

        // ---- xz gemv: lane computes xc cols 4lane+q and z cols 128+4lane+q ----
        ull axc[4][2], az[4][2];
#pragma unroll
        for (int j = 0; j < 4; j++) { axc[j][0] = axc[j][1] = 0ULL; az[j][0] = az[j][1] = 0ULL; }
#pragma unroll 2
        for (int i0 = 0; i0 < 64; i0 += 4) {
            float4 xv0 = *(const float4*)&s.xs[w][0][i0];
            float4 xv1 = *(const float4*)&s.xs[w][1][i0];
            float4 xv2 = *(const float4*)&s.xs[w][2][i0];
            float4 xv3 = *(const float4*)&s.xs[w][3][i0];
#pragma unroll
            for (int u = 0; u < 4; u++) {
                const float* wr = &s.ipw[(i0 + u) * 256];
                float4 wxc = *(const float4*)&wr[4 * lane];
                float4 wz  = *(const float4*)&wr[128 + 4 * lane];
                ull wxc01 = pk2(wxc.x, wxc.y), wxc23 = pk2(wxc.z, wxc.w);
                ull wz01  = pk2(wz.x, wz.y),   wz23  = pk2(wz.z, wz.w);
                float f0 = (u == 0 ? xv0.x : u == 1 ? xv0.y : u == 2 ? xv0.z : xv0.w);
                float f1 = (u == 0 ? xv1.x : u == 1 ? xv1.y : u == 2 ? xv1.z : xv1.w);
                float f2 = (u == 0 ? xv2.x : u == 1 ? xv2.y : u == 2 ? xv2.z : xv2.w);
                float f3 = (u == 0 ? xv3.x : u == 1 ? xv3.y : u == 2 ? xv3.z : xv3.w);
                ull p0 = pk2(f0, f0), p1 = pk2(f1, f1), p2 = pk2(f2, f2), p3 = pk2(f3, f3);
                axc[0][0] = ffma2(wxc01, p0, axc[0][0]); axc[0][1] = ffma2(wxc23, p0, axc[0][1]);
                az [0][0] = ffma2(wz01,  p0, az [0][0]); az [0][1] = ffma2(wz23,  p0, az [0][1]);
                axc[1][0] = ffma2(wxc01, p1, axc[1][0]); axc[1][1] = ffma2(wxc23, p1, axc[1][1]);
                az [1][0] = ffma2(wz01,  p1, az [1][0]); az [1][1] = ffma2(wz23,  p1, az [1][1]);
                axc[2][0] = ffma2(wxc01, p2, axc[2][0]); axc[2][1] = ffma2(wxc23, p2, axc[2][1]);
                az [2][0] = ffma2(wz01,  p2, az [2][0]); az [2][1] = ffma2(wz23,  p2, az [2][1]);
                axc[3][0] = ffma2(wxc01, p3, axc[3][0]); axc[3][1] = ffma2(wxc23, p3, axc[3][1]);
                az [3][0] = ffma2(wz01,  p3, az [3][0]); az [3][1] = ffma2(wz23,  p3, az [3][1]);
            }
        }

        // ---- conv (only k=3 tap survives at L=1) + silu; silu(z) ----
        float xc[4][4], sz[4][4];
        {
            float4 cwv = *(const float4*)&s.cw3[4 * lane];
            float4 cbv = *(const float4*)&s.cb[4 * lane];
#pragma unroll
            for (int j = 0; j < 4; j++) {
                float a0, a1, a2, a3, z0, z1, z2, z3;
                upk2(axc[j][0], a0, a1); upk2(axc[j][1], a2, a3);
                upk2(az[j][0], z0, z1);  upk2(az[j][1], z2, z3);
                xc[j][0] = siluf(fmaf(a0, cwv.x, cbv.x));
                xc[j][1] = siluf(fmaf(a1, cwv.y, cbv.y));
                xc[j][2] = siluf(fmaf(a2, cwv.z, cbv.z));
                xc[j][3] = siluf(fmaf(a3, cwv.w, cbv.w));
                sz[j][0] = siluf(z0); sz[j][1] = siluf(z1);
                sz[j][2] = siluf(z2); sz[j][3] = siluf(z3);
            }
        }

        // ---- stage xc for the 128->36 projection ----
#pragma unroll
        for (int j = 0; j < 4; j++)
            *(float4*)&s.sc[w][j][4 * lane] = make_float4(xc[j][0], xc[j][1], xc[j][2], xc[j][3]);
        __syncwarp();

        // ---- dt pre-projection (rows 0..3) via butterfly reduction ----
        float pr[4][4];   // [r][job]
#pragma unroll
        for (int r = 0; r < 4; r++) {
            const float* wr = &s.xpwT[r * XPW_S + 4 * lane];
            float w0 = wr[0], w1 = wr[1], w2 = wr[2], w3 = wr[3];
#pragma unroll
            for (int j = 0; j < 4; j++) {
                float p = xc[j][0] * w0 + xc[j][1] * w1 + xc[j][2] * w2 + xc[j][3] * w3;
                pr[r][j] = warp_sum(p);
            }
        }
        float dts[4][4];
        {
            float4 dtbv = *(const float4*)&s.dtb[4 * lane];
#pragma unroll
            for (int j = 0; j < 4; j++) {
                dts[j][0] = dtbv.x; dts[j][1] = dtbv.y; dts[j][2] = dtbv.z; dts[j][3] = dtbv.w;
            }
#pragma unroll
            for (int r = 0; r < 4; r++) {
                float4 dwv = *(const float4*)&s.dtw[r * 128 + 4 * lane];
#pragma unroll
                for (int j = 0; j < 4; j++) {
                    dts[j][0] = fmaf(pr[r][j], dwv.x, dts[j][0]);
                    dts[j][1] = fmaf(pr[r][j], dwv.y, dts[j][1]);
                    dts[j][2] = fmaf(pr[r][j], dwv.z, dts[j][2]);
                    dts[j][3] = fmaf(pr[r][j], dwv.w, dts[j][3]);
                }
            }
#pragma unroll
            for (int j = 0; j < 4; j++) {
                dts[j][0] = softplusf(dts[j][0]); dts[j][1] = softplusf(dts[j][1]);
                dts[j][2] = softplusf(dts[j][2]); dts[j][3] = softplusf(dts[j][3]);
            }
        }

        // ---- B/C rows: lane computes row 4+lane (lanes 0-15: B[s], 16-31: C[s]) ----
        ull a01 = 0ULL, a23 = 0ULL;
        {
            const float* wrow = &s.xpwT[(4 + lane) * XPW_S];
#pragma unroll 4
            for (int d0 = 0; d0 < 128; d0 += 4) {
                float4 c0 = *(const float4*)&s.sc[w][0][d0];
                float4 c1 = *(const float4*)&s.sc[w][1][d0];
                float4 c2 = *(const float4*)&s.sc[w][2][d0];
                float4 c3 = *(const float4*)&s.sc[w][3][d0];
                float w0 = wrow[d0], w1 = wrow[d0 + 1], w2 = wrow[d0 + 2], w3 = wrow[d0 + 3];
                a01 = ffma2(pk2(c0.x, c1.x), pk2(w0, w0), a01);
                a23 = ffma2(pk2(c2.x, c3.x), pk2(w0, w0), a23);
                a01 = ffma2(pk2(c0.y, c1.y), pk2(w1, w1), a01);
                a23 = ffma2(pk2(c2.y, c3.y), pk2(w1, w1), a23);
                a01 = ffma2(pk2(c0.z, c1.z), pk2(w2, w2), a01);
                a23 = ffma2(pk2(c2.z, c3.z), pk2(w2, w2), a23);
                a01 = ffma2(pk2(c0.w, c1.w), pk2(w3, w3), a01);
                a23 = ffma2(pk2(c2.w, c3.w), pk2(w3, w3), a23);
            }
        }
        float bc[4];
        upk2(a01, bc[0], bc[1]); upk2(a23, bc[2], bc[3]);
#pragma unroll
        for (int j = 0; j < 4; j++) {
            float other = __shfl_xor_sync(0xffffffffu, bc[j], 16);
            bc[j] = half_sum(bc[j] * other);   // BC = sum_s B[s]*C[s], broadcast to all lanes
        }

        // ---- y = xc*(dt*BC + dskip)*silu(z); restage into sc ----
        {
            float4 dsv = *(const float4*)&s.dskip[4 * lane];
            __syncwarp();   // all lanes finished reading xc from sc
#pragma unroll
            for (int j = 0; j < 4; j++) {
                float4 yv;
                yv.x = xc[j][0] * fmaf(dts[j][0], bc[j], dsv.x) * sz[j][0];
                yv.y = xc[j][1] * fmaf(dts[j][1], bc[j], dsv.y) * sz[j][1];
                yv.z = xc[j][2] * fmaf(dts[j][2], bc[j], dsv.z) * sz[j][2];
                yv.w = xc[j][3] * fmaf(dts[j][3], bc[j], dsv.w) * sz[j][3];
                *(float4*)&s.sc[w][j][4 * lane] = yv;
            }
            __syncwarp();
        }

        // ---- out-proj gemv: 128 -> 64, lane owns out dims {2lane, 2lane+1} ----
        ull aco[4] = {0ULL, 0ULL, 0ULL, 0ULL};
#pragma unroll 4
        for (int d0 = 0; d0 < 128; d0 += 4) {
            float4 y0 = *(const float4*)&s.sc[w][0][d0];
            float4 y1 = *(const float4*)&s.sc[w][1][d0];
            float4 y2 = *(const float4*)&s.sc[w][2][d0];
            float4 y3 = *(const float4*)&s.sc[w][3][d0];
#pragma unroll
            for (int q = 0; q < 4; q++) {
                float2 w2 = *(const float2*)&s.opw[(d0 + q) * 64 + 2 * lane];
                ull wp = pk2(w2.x, w2.y);
                float f0 = (q == 0 ? y0.x : q == 1 ? y0.y : q == 2 ? y0.z : y0.w);
                float f1 = (q == 0 ? y1.x : q == 1 ? y1.y : q == 2 ? y1.z : y1.w);
                float f2 = (q == 0 ? y2.x : q == 1 ? y2.y : q == 2 ? y2.z : y2.w);
                float f3 = (q == 0 ? y3.x : q == 1 ? y3.y : q == 2 ? y3.z : y3.w);
                aco[0] = ffma2(wp, pk2(f0, f0), aco[0]);
                aco[1] = ffma2(wp, pk2(f1, f1), aco[1]);
                aco[2] = ffma2(wp, pk2(f2, f2), aco[2]);
                aco[3] = ffma2(wp, pk2(f3, f3), aco[3]);
            }
        }

        // ---- layernorm over 64 dims + residual ----
        {
            float2 gv = *(const float2*)&s.lng[2 * lane];
            float2 bv = *(const float2*)&s.lnb[2 * lane];
#pragma unroll
            for (int j = 0; j < 4; j++) {
                float o0, o1;
                upk2(aco[j], o0, o1);
                float m  = warp_sum(o0 + o1) * (1.0f / 64.0f);
                float m2 = warp_sum(o0 * o0 + o1 * o1) * (1.0f / 64.0f);
                float rs = rsqrtf(m2 - m * m + EPSV);
                x_[j][0] += (o0 - m) * rs * gv.x + bv.x;
                x_[j][1] += (o1 - m) * rs * gv.y + bv.y;
            }
        }
    }

    // ================= head =================
#pragma unroll
    for (int j = 0; j < 4; j++)
        *(float2*)&s.xs[w][j][2 * lane] = make_float2(x_[j][0], x_[j][1]);
    __syncthreads();                                  // all layer weight reads done
    for (int i = t; i < 4096; i += THREADS) s.ipw[i] = hw1[i];   // head_w1 [128][32]
    if (t < 32) { s.cw3[t] = hb1[t]; s.cb[t] = hw2[t]; }
    __syncthreads();

    float b2v = hb2[0];
#pragma unroll
    for (int e = 0; e < 2; e++) {
        float h = s.cw3[lane];
        const float* hn = s.xs[w][2 * e + 0];
        const float* hr = s.xs[w][2 * e + 1];
#pragma unroll 8
        for (int k = 0; k < 64; k++) h = fmaf(hn[k], s.ipw[k * 32 + lane], h);
#pragma unroll 8
        for (int k = 0; k < 64; k++) h = fmaf(hr[k], s.ipw[(64 + k) * 32 + lane], h);
        h = fmaxf(h, 0.0f);
        float v = warp_sum(h * s.cb[lane]);
        if (lane == 0) out[e0 + e] = v + b2v;
    }
}

extern "C" void kernel_launch(void* const* d_in, const int* in_sizes, int n_in,
                              void* d_out, int out_size) {
    const float* x        = (const float*)d_in[0];
    const float* w_nr     = (const float*)d_in[1];
    const float* b_nr     = (const float*)d_in[2];
    const float* w_r      = (const float*)d_in[3];
    const float* b_r      = (const float*)d_in[4];
    const float* w_in_nr  = (const float*)d_in[5];
    const float* b_in_nr  = (const float*)d_in[6];
    const float* w_in_r   = (const float*)d_in[7];
    const float* b_in_r   = (const float*)d_in[8];
    const float* ipw      = (const float*)d_in[9];
    const float* cw       = (const float*)d_in[10];
    const float* cb       = (const float*)d_in[11];
    const float* xpw      = (const float*)d_in[12];
    const float* dtw      = (const float*)d_in[13];
    const float* dtb      = (const float*)d_in[14];
    /* alog d_in[15] is dead code at L=1 (scan h0=0) */
    const float* dskip    = (const float*)d_in[16];
    const float* opw      = (const float*)d_in[17];
    const float* lng      = (const float*)d_in[18];
    const float* lnb      = (const float*)d_in[19];
    const float* hw1      = (const float*)d_in[20];
    const float* hb1      = (const float*)d_in[21];
    const float* hw2      = (const float*)d_in[22];
    const float* hb2      = (const float*)d_in[23];

    size_t smem = sizeof(Smem);
    cudaFuncSetAttribute((const void*)mamba_main,
                         cudaFuncAttributeMaxDynamicSharedMemorySize, (int)smem);

    prep_kernel<<<144, 256>>>(w_nr, b_nr, w_r, b_r, w_in_nr, b_in_nr, w_in_r, b_in_r);
    mamba_main<<<NBLK, THREADS, smem>>>(x, ipw, cw, cb, xpw, dtw, dtb, dskip, opw,
                                        lng, lnb, hw1, hb1, hw2, hb2, (float*)d_out);
}